// round 3
// baseline (speedup 1.0000x reference)
#include <cuda_runtime.h>
#include <float.h>

#define BB 4096
#define NN 2048
#define NPAIR 3
#define ROW_THREADS 256
#define NBLOCKS (BB * NPAIR)

// Per-(pair,row) weighted contributions + completion ticket.
// Final sum is fixed-order (i ascending) -> deterministic output.
__device__ float g_partials[NPAIR * BB];
__device__ unsigned int g_count = 0;

__global__ __launch_bounds__(ROW_THREADS)
void wnrmse_kernel(const float* __restrict__ o1, const float* __restrict__ t1,
                   const float* __restrict__ o2, const float* __restrict__ t2,
                   const float* __restrict__ o3, const float* __restrict__ t3,
                   float* __restrict__ out) {
    const int b = blockIdx.x;   // batch row
    const int p = blockIdx.y;   // pair index
    const int tid = threadIdx.x;
    const int w = tid >> 5, l = tid & 31;

    const float* o = (p == 0) ? o1 : ((p == 1) ? o2 : o3);
    const float* t = (p == 0) ? t1 : ((p == 1) ? t2 : t3);

    const float4* __restrict__ o4 = reinterpret_cast<const float4*>(o + (size_t)b * NN);
    const float4* __restrict__ t4 = reinterpret_cast<const float4*>(t + (size_t)b * NN);

    // 2048 floats = 512 float4; 256 threads -> 2 float4 each. Front-batch all 4 loads.
    float4 ov0 = o4[tid];
    float4 tv0 = t4[tid];
    float4 ov1 = o4[tid + ROW_THREADS];
    float4 tv1 = t4[tid + ROW_THREADS];

    float ssq = 0.0f, tmax = -FLT_MAX, tmin = FLT_MAX;
    {
        float d;
        d = ov0.x - tv0.x; ssq = fmaf(d, d, ssq); tmax = fmaxf(tmax, tv0.x); tmin = fminf(tmin, tv0.x);
        d = ov0.y - tv0.y; ssq = fmaf(d, d, ssq); tmax = fmaxf(tmax, tv0.y); tmin = fminf(tmin, tv0.y);
        d = ov0.z - tv0.z; ssq = fmaf(d, d, ssq); tmax = fmaxf(tmax, tv0.z); tmin = fminf(tmin, tv0.z);
        d = ov0.w - tv0.w; ssq = fmaf(d, d, ssq); tmax = fmaxf(tmax, tv0.w); tmin = fminf(tmin, tv0.w);
        d = ov1.x - tv1.x; ssq = fmaf(d, d, ssq); tmax = fmaxf(tmax, tv1.x); tmin = fminf(tmin, tv1.x);
        d = ov1.y - tv1.y; ssq = fmaf(d, d, ssq); tmax = fmaxf(tmax, tv1.y); tmin = fminf(tmin, tv1.y);
        d = ov1.z - tv1.z; ssq = fmaf(d, d, ssq); tmax = fmaxf(tmax, tv1.z); tmin = fminf(tmin, tv1.z);
        d = ov1.w - tv1.w; ssq = fmaf(d, d, ssq); tmax = fmaxf(tmax, tv1.w); tmin = fminf(tmin, tv1.w);
    }

    // Intra-warp reduce (3 values)
    #pragma unroll
    for (int s = 16; s > 0; s >>= 1) {
        ssq  += __shfl_xor_sync(0xFFFFFFFFu, ssq,  s);
        tmax  = fmaxf(tmax, __shfl_xor_sync(0xFFFFFFFFu, tmax, s));
        tmin  = fminf(tmin, __shfl_xor_sync(0xFFFFFFFFu, tmin, s));
    }

    // Cross-warp reduce (8 warps)
    __shared__ float s_ssq[8], s_max[8], s_min[8];
    if (l == 0) { s_ssq[w] = ssq; s_max[w] = tmax; s_min[w] = tmin; }
    __syncthreads();

    if (tid == 0) {
        float a = s_ssq[0], mx = s_max[0], mn = s_min[0];
        #pragma unroll
        for (int i = 1; i < 8; i++) {
            a += s_ssq[i];
            mx = fmaxf(mx, s_max[i]);
            mn = fminf(mn, s_min[i]);
        }
        const float wgt = (p == 0) ? 0.5f : 0.25f;
        g_partials[p * BB + b] = wgt * sqrtf(a * (1.0f / NN)) / (mx - mn);
        __threadfence();
    }
    __syncthreads();

    // Ticket: the last CTA to finish performs the fixed-order final reduction.
    __shared__ unsigned int s_ticket;
    if (tid == 0) s_ticket = atomicAdd(&g_count, 1u);
    __syncthreads();

    if (s_ticket == (unsigned)(NBLOCKS - 1)) {
        __threadfence();   // acquire: see all g_partials writes
        float s = 0.0f;
        #pragma unroll
        for (int i = tid; i < NPAIR * BB; i += ROW_THREADS) s += g_partials[i];

        #pragma unroll
        for (int sh = 16; sh > 0; sh >>= 1)
            s += __shfl_xor_sync(0xFFFFFFFFu, s, sh);

        __shared__ float s_fin[8];
        if (l == 0) s_fin[w] = s;
        __syncthreads();
        if (tid == 0) {
            float a = s_fin[0];
            #pragma unroll
            for (int i = 1; i < 8; i++) a += s_fin[i];
            out[0] = a * (1.0f / BB);
            g_count = 0;   // reset for next graph replay
        }
    }
}

extern "C" void kernel_launch(void* const* d_in, const int* in_sizes, int n_in,
                              void* d_out, int out_size) {
    const float* o1 = (const float*)d_in[0];
    const float* t1 = (const float*)d_in[1];
    const float* o2 = (const float*)d_in[2];
    const float* t2 = (const float*)d_in[3];
    const float* o3 = (const float*)d_in[4];
    const float* t3 = (const float*)d_in[5];
    float* out = (float*)d_out;

    dim3 grid(BB, NPAIR);
    wnrmse_kernel<<<grid, ROW_THREADS>>>(o1, t1, o2, t2, o3, t3, out);
}